// round 15
// baseline (speedup 1.0000x reference)
#include <cuda_runtime.h>
#include <cuda_fp16.h>
#include <cstdint>
#include <math.h>

#define D_MODEL 1024
#define NHEADS  16
#define HD      64
#define BATCH   2
#define SEQ     2048
#define MTOK    (BATCH * SEQ)   // 4096
#define QSCALE  (0.125f * 1.4426950408889634f)   // 1/sqrt(64) * log2(e)

// fp16 intermediates (device globals; no allocation allowed)
__device__ __half h_qin[MTOK * D_MODEL];
__device__ __half h_kin[MTOK * D_MODEL];
__device__ __half h_vin[MTOK * D_MODEL];
__device__ __half h_wq[D_MODEL * D_MODEL];
__device__ __half h_wk[D_MODEL * D_MODEL];
__device__ __half h_wv[D_MODEL * D_MODEL];
__device__ __half h_wo[D_MODEL * D_MODEL];
__device__ __half g_qh[MTOK * D_MODEL];   // Q proj (pre-scaled by QSCALE)
__device__ __half g_kh[MTOK * D_MODEL];
__device__ __half g_vh[MTOK * D_MODEL];
__device__ __half g_ch[MTOK * D_MODEL];   // attention context

__device__ __forceinline__ uint32_t pack_h2(float lo, float hi) {
    __half2 h = __floats2half2_rn(lo, hi);
    return *(uint32_t*)&h;
}

__device__ __forceinline__ uint32_t h2ex2(uint32_t s) {
    uint32_t y;
    asm("ex2.approx.f16x2 %0, %1;" : "=r"(y) : "r"(s));
    return y;
}

__device__ __forceinline__ uint32_t h2add(uint32_t a, uint32_t b) {
    uint32_t y;
    asm("add.f16x2 %0, %1, %2;" : "=r"(y) : "r"(a), "r"(b));
    return y;
}

__device__ __forceinline__ void mma_f16(float* d, const uint32_t* a, const uint32_t* b) {
    asm volatile(
        "mma.sync.aligned.m16n8k16.row.col.f32.f16.f16.f32 "
        "{%0,%1,%2,%3}, {%4,%5,%6,%7}, {%8,%9}, {%0,%1,%2,%3};"
        : "+f"(d[0]), "+f"(d[1]), "+f"(d[2]), "+f"(d[3])
        : "r"(a[0]), "r"(a[1]), "r"(a[2]), "r"(a[3]), "r"(b[0]), "r"(b[1]));
}

__device__ __forceinline__ void ldsm_x4(uint32_t* r, uint32_t saddr) {
    asm volatile(
        "ldmatrix.sync.aligned.m8n8.x4.shared.b16 {%0,%1,%2,%3}, [%4];"
        : "=r"(r[0]), "=r"(r[1]), "=r"(r[2]), "=r"(r[3]) : "r"(saddr));
}

__device__ __forceinline__ void ldsm_x4_t(uint32_t* r, uint32_t saddr) {
    asm volatile(
        "ldmatrix.sync.aligned.m8n8.x4.trans.shared.b16 {%0,%1,%2,%3}, [%4];"
        : "=r"(r[0]), "=r"(r[1]), "=r"(r[2]), "=r"(r[3]) : "r"(saddr));
}

__device__ __forceinline__ uint32_t smem_u32(const void* p) {
    uint32_t a;
    asm("{ .reg .u64 t; cvta.to.shared.u64 t, %1; cvt.u32.u64 %0, t; }"
        : "=r"(a) : "l"(p));
    return a;
}

#define CP16(dst, src) \
    asm volatile("cp.async.cg.shared.global [%0], [%1], 16;" :: "r"(dst), "l"(src))
#define CP_COMMIT() asm volatile("cp.async.commit_group;" ::: "memory")
#define CP_WAIT(n)  asm volatile("cp.async.wait_group %0;" :: "n"(n) : "memory")

// ===========================================================================
// Fused fp32 -> fp16 convert, ONE launch, 8 independent f4 per thread (MLP=8).
// Tensor boundaries are multiples of 262144 (divisible by 2048), so each
// block's 2048-index window lies in exactly one tensor per iteration slot.
// ===========================================================================
#define N4_IN 1048576
#define N4_W  262144
#define N4_TOTAL (3 * N4_IN + 4 * N4_W)   // 4194304

__global__ void __launch_bounds__(256) cvt_all_kernel(
    const float4* __restrict__ q, const float4* __restrict__ k,
    const float4* __restrict__ v, const float4* __restrict__ wq,
    const float4* __restrict__ wk, const float4* __restrict__ wv,
    const float4* __restrict__ wo)
{
    const int base = blockIdx.x * 2048 + threadIdx.x;
#pragma unroll
    for (int u = 0; u < 8; u++) {
        int i = base + u * 256;
        const float4* src;
        uint2* dst;
        int j;
        if (i < 3 * N4_IN) {
            int t = i / N4_IN;
            j = i - t * N4_IN;
            src = (t == 0) ? q : (t == 1) ? k : v;
            dst = (uint2*)((t == 0) ? h_qin : (t == 1) ? h_kin : h_vin);
        } else {
            int r = i - 3 * N4_IN;
            int t = r / N4_W;
            j = r - t * N4_W;
            src = (t == 0) ? wq : (t == 1) ? wk : (t == 2) ? wv : wo;
            dst = (uint2*)((t == 0) ? h_wq : (t == 1) ? h_wk : (t == 2) ? h_wv : h_wo);
        }
        float4 val = src[j];
        dst[j] = make_uint2(pack_h2(val.x, val.y), pack_h2(val.z, val.w));
    }
}

// ===========================================================================
// fp16 GEMM (R13 winner): C[M][N] = A[M][K] * W[N][K]^T
// CTA 128x128, 3-stage cp.async pipeline, interleaved prefetch.
// ===========================================================================
#define GK 1024
#define GN 1024
#define GST 144               // smem row stride bytes (64 halves + 8 pad)
#define GSTW 36
#define GABUF (128 * GSTW)    // words per A (or B) stage
#define GW_B  (3 * GABUF)     // B region word offset
#define GSM_TOT (6 * GABUF * 4)   // 110592 bytes
#define NKIT (GK / 64)        // 16

__global__ void __launch_bounds__(256, 2) gemm_h_kernel(
    const float* __restrict__ bias, float* __restrict__ Cf, int baseSel)
{
    extern __shared__ uint32_t gsm[];
    const uint32_t smb = smem_u32(gsm);
    const int sel = baseSel + blockIdx.z;

    const __half* A;
    const __half* W;
    __half* Ch = nullptr;
    if (sel == 0)      { A = h_qin; W = h_wq; Ch = g_qh; }
    else if (sel == 1) { A = h_kin; W = h_wk; Ch = g_kh; }
    else if (sel == 2) { A = h_vin; W = h_wv; Ch = g_vh; }
    else               { A = g_ch;  W = h_wo; }

    const int tid = threadIdx.x;
    const int wid = tid >> 5;
    const int lane = tid & 31;
    const int g   = lane >> 2;
    const int tig = lane & 3;
    const int wm = wid >> 2;
    const int wn = wid & 3;
    const int bm = blockIdx.y * 128;
    const int bn = blockIdx.x * 128;

    const uint32_t aofs = (uint32_t)(wm * 64 + (lane & 15)) * GST + ((lane >> 4) & 1) * 16;
    const uint32_t bofs = (uint32_t)(wn * 32 + (lane & 7) + ((lane >> 4) & 1) * 8) * GST +
                          ((lane >> 3) & 1) * 16;

    auto issue_stage = [&](int k0, int st) {
        const uint32_t ab = smb + (uint32_t)(st * GABUF) * 4;
        const uint32_t bb = smb + (uint32_t)(GW_B + st * GABUF) * 4;
#pragma unroll
        for (int i = 0; i < 4; i++) {
            int f = tid + i * 256;
            int r = f >> 3;
            int c = f & 7;
            CP16(ab + (uint32_t)r * GST + c * 16, A + (size_t)(bm + r) * GK + k0 + c * 8);
            CP16(bb + (uint32_t)r * GST + c * 16, W + (size_t)(bn + r) * GK + k0 + c * 8);
        }
    };

    float acc[4][4][4];
#pragma unroll
    for (int i = 0; i < 4; i++)
#pragma unroll
        for (int j = 0; j < 4; j++)
#pragma unroll
            for (int r = 0; r < 4; r++) acc[i][j][r] = 0.f;

    issue_stage(0, 0);
    CP_COMMIT();
    issue_stage(64, 1);
    CP_COMMIT();

    for (int k = 0; k < NKIT; k++) {
        if (k + 1 < NKIT) CP_WAIT(1); else CP_WAIT(0);
        __syncthreads();

        const int cur = k % 3;
        const uint32_t Ab = smb + (uint32_t)(cur * GABUF) * 4 + aofs;
        const uint32_t Bb = smb + (uint32_t)(GW_B + cur * GABUF) * 4 + bofs;

        const bool pre = (k + 2 < NKIT);
        const int nst = (k + 2) % 3;
        const uint32_t abp = smb + (uint32_t)(nst * GABUF) * 4;
        const uint32_t bbp = smb + (uint32_t)(GW_B + nst * GABUF) * 4;
        const __half* An = A + (size_t)bm * GK + (k + 2) * 64;
        const __half* Wn = W + (size_t)bn * GK + (k + 2) * 64;

#pragma unroll
        for (int kg = 0; kg < 4; kg++) {
            uint32_t afr[4][4];
#pragma unroll
            for (int mi = 0; mi < 4; mi++)
                ldsm_x4(afr[mi], Ab + (uint32_t)(mi * 16) * GST + kg * 32);
            uint32_t bq[2][4];
#pragma unroll
            for (int nb = 0; nb < 2; nb++)
                ldsm_x4(bq[nb], Bb + (uint32_t)(nb * 16) * GST + kg * 32);
#pragma unroll
            for (int mi = 0; mi < 4; mi++) {
                mma_f16(acc[mi][0], afr[mi], bq[0]);
                mma_f16(acc[mi][1], afr[mi], bq[0] + 2);
                mma_f16(acc[mi][2], afr[mi], bq[1]);
                mma_f16(acc[mi][3], afr[mi], bq[1] + 2);
            }
            if (pre) {
                int f = tid + kg * 256;
                int r = f >> 3;
                int c = f & 7;
                CP16(abp + (uint32_t)r * GST + c * 16, An + (size_t)r * GK + c * 8);
                CP16(bbp + (uint32_t)r * GST + c * 16, Wn + (size_t)r * GK + c * 8);
            }
        }
        if (pre) CP_COMMIT();
    }

    if (sel < 3) {
        const float sc = (sel == 0) ? QSCALE : 1.f;
#pragma unroll
        for (int mi = 0; mi < 4; mi++)
#pragma unroll
            for (int ni = 0; ni < 4; ni++) {
                int row = bm + wm * 64 + mi * 16 + g;
                int col = bn + wn * 32 + ni * 8 + 2 * tig;
                *(uint32_t*)&Ch[(size_t)row * GN + col] =
                    pack_h2(acc[mi][ni][0] * sc, acc[mi][ni][1] * sc);
                *(uint32_t*)&Ch[(size_t)(row + 8) * GN + col] =
                    pack_h2(acc[mi][ni][2] * sc, acc[mi][ni][3] * sc);
            }
    } else {
#pragma unroll
        for (int mi = 0; mi < 4; mi++)
#pragma unroll
            for (int ni = 0; ni < 4; ni++) {
                int row = bm + wm * 64 + mi * 16 + g;
                int col = bn + wn * 32 + ni * 8 + 2 * tig;
                float2 bb = *(const float2*)&bias[col];
                *(float2*)&Cf[(size_t)row * GN + col] =
                    make_float2(acc[mi][ni][0] + bb.x, acc[mi][ni][1] + bb.y);
                *(float2*)&Cf[(size_t)(row + 8) * GN + col] =
                    make_float2(acc[mi][ni][2] + bb.x, acc[mi][ni][3] + bb.y);
            }
    }
}

// ===========================================================================
// fp16 flash attention (R14 winner): max-free f16x2-exp softmax, 128-key
// macro-tiles, 2-stage cp.async KV double buffer, interleaved KV prefetch.
// ===========================================================================
#define NT2 (SEQ / 128)            // 16 macro-tiles
#define ATSB 144
#define ATSW 36
#define W_K   (128 * ATSW)         // K region word offset (after Q/P)
#define KBUF2 (128 * ATSW)         // words per 128-row K (or V) stage
#define W_V   (W_K + 2 * KBUF2)
#define W_MB  (W_V + 2 * KBUF2)    // 64 mask bitmask words
#define ATT_SM_BYTES ((W_MB + 64) * 4)   // 92416

__global__ void __launch_bounds__(256, 2) attn_kernel(const int* __restrict__ mask)
{
    extern __shared__ uint32_t smw[];
    const uint32_t smb = smem_u32(smw);

    const int tid = threadIdx.x;
    const int wid = tid >> 5;
    const int lane = tid & 31;
    const int g   = lane >> 2;
    const int tig = lane & 3;
    const int bh = blockIdx.y;
    const int b = bh >> 4;
    const int h = bh & 15;
    const int q0 = blockIdx.x * 128;
    const int r0 = wid * 16 + g;

    const __half* Qg = g_qh + ((size_t)b * SEQ + q0) * D_MODEL + h * HD;
    const __half* Kg = g_kh + (size_t)b * SEQ * D_MODEL + h * HD;
    const __half* Vg = g_vh + (size_t)b * SEQ * D_MODEL + h * HD;
    const int* mrow = mask + b * SEQ;

    const uint32_t kofs = (uint32_t)((lane & 7) + ((lane >> 4) & 1) * 8) * ATSB +
                          ((lane >> 3) & 1) * 16;
    const uint32_t pofs = (uint32_t)(wid * 16 + (lane & 15)) * ATSB +
                          ((lane >> 4) & 1) * 16;
    const uint32_t vofs = (uint32_t)((lane & 7) + ((lane >> 3) & 1) * 8) * ATSB +
                          ((lane >> 4) & 1) * 16;

    auto issue_kv = [&](int t, int st) {
        const __half* Kt = Kg + (size_t)t * 128 * D_MODEL;
        const __half* Vt = Vg + (size_t)t * 128 * D_MODEL;
        const uint32_t kb = smb + (uint32_t)(W_K + st * KBUF2) * 4;
        const uint32_t vb = smb + (uint32_t)(W_V + st * KBUF2) * 4;
#pragma unroll
        for (int i = 0; i < 4; i++) {
            int f = tid + i * 256;
            int r = f >> 3;
            int c = f & 7;
            CP16(kb + (uint32_t)r * ATSB + c * 16, Kt + (size_t)r * D_MODEL + c * 8);
            CP16(vb + (uint32_t)r * ATSB + c * 16, Vt + (size_t)r * D_MODEL + c * 8);
        }
    };

    // ---- prologue: Q (group 0), macro-tile 0 (group 1), mask ballots ----
#pragma unroll
    for (int i = 0; i < 4; i++) {
        int f = tid + i * 256;
        int r = f >> 3;
        int c = f & 7;
        CP16(smb + (uint32_t)r * ATSB + c * 16, Qg + (size_t)r * D_MODEL + c * 8);
    }
    CP_COMMIT();
    issue_kv(0, 0);
    CP_COMMIT();

#pragma unroll
    for (int i = 0; i < 8; i++) {
        int w = wid * 8 + i;
        uint32_t bal = __ballot_sync(0xFFFFFFFF, mrow[w * 32 + lane] != 0);
        if (lane == 0) smw[W_MB + w] = bal;
    }

    CP_WAIT(1);               // Q staged (tile 0 may still be in flight)
    __syncthreads();

    uint32_t qf[4][4];
#pragma unroll
    for (int kg = 0; kg < 4; kg++) {
        qf[kg][0] = smw[r0 * ATSW + kg * 8 + tig];
        qf[kg][1] = smw[(r0 + 8) * ATSW + kg * 8 + tig];
        qf[kg][2] = smw[r0 * ATSW + kg * 8 + tig + 4];
        qf[kg][3] = smw[(r0 + 8) * ATSW + kg * 8 + tig + 4];
    }

    float oacc[8][4];
#pragma unroll
    for (int i = 0; i < 8; i++)
#pragma unroll
        for (int j = 0; j < 4; j++) oacc[i][j] = 0.f;
    float l0 = 0.f, l1 = 0.f;

    for (int t = 0; t < NT2; t++) {
        CP_WAIT(0);
        __syncthreads();

        const int cur = t & 1;
        const uint32_t Kb = smb + (uint32_t)(W_K + cur * KBUF2) * 4 + kofs;
        const uint32_t Vb = smb + (uint32_t)(W_V + cur * KBUF2) * 4 + vofs;

        const bool pre = (t + 1 < NT2);
        const int nst = (t + 1) & 1;
        const __half* Kn = Kg + (size_t)(t + 1) * 128 * D_MODEL;
        const __half* Vn = Vg + (size_t)(t + 1) * 128 * D_MODEL;
        const uint32_t kbp = smb + (uint32_t)(W_K + nst * KBUF2) * 4;
        const uint32_t vbp = smb + (uint32_t)(W_V + nst * KBUF2) * 4;

        uint32_t lacc0 = 0u, lacc1 = 0u;   // half2 partial l accumulators

#pragma unroll
        for (int hf = 0; hf < 2; hf++) {
            const uint32_t mb0 = smw[W_MB + 4 * t + 2 * hf];
            const uint32_t mb1 = smw[W_MB + 4 * t + 2 * hf + 1];
            const uint32_t rowoff = (uint32_t)(hf * 64) * ATSB;

            // ---- S = Q K^T (log2 domain) ----
            float sacc[8][4];
#pragma unroll
            for (int i = 0; i < 8; i++)
#pragma unroll
                for (int j = 0; j < 4; j++) sacc[i][j] = 0.f;
#pragma unroll
            for (int kg = 0; kg < 4; kg++) {
#pragma unroll
                for (int nib = 0; nib < 8; nib += 2) {
                    uint32_t kf[4];
                    ldsm_x4(kf, Kb + rowoff + (uint32_t)(nib * 8) * ATSB + kg * 32);
                    mma_f16(sacc[nib],     qf[kg], kf);
                    mma_f16(sacc[nib + 1], qf[kg], kf + 2);
                }
                if (pre) {
                    int s = hf * 4 + kg;
                    int ch = (s < 4) ? s : (s - 4);
                    int f = tid + ch * 256;
                    int r = f >> 3;
                    int c = f & 7;
                    if (s < 4) {
                        CP16(kbp + (uint32_t)r * ATSB + c * 16,
                             Kn + (size_t)r * D_MODEL + c * 8);
                    } else {
                        CP16(vbp + (uint32_t)r * ATSB + c * 16,
                             Vn + (size_t)r * D_MODEL + c * 8);
                    }
                }
            }

            // ---- max-free softmax, f16x2 exp: p = (2^s) & maskword ----
#pragma unroll
            for (int ni = 0; ni < 8; ni++) {
                uint32_t mb = (ni < 4) ? mb0 : mb1;
                int c0 = (ni * 8 + 2 * tig) & 31;
                uint32_t mw = (((mb >> c0) & 1) ? 0x0000FFFFu : 0u) |
                              (((mb >> (c0 + 1)) & 1) ? 0xFFFF0000u : 0u);
                uint32_t p01 = h2ex2(pack_h2(sacc[ni][0], sacc[ni][1])) & mw;
                uint32_t p23 = h2ex2(pack_h2(sacc[ni][2], sacc[ni][3])) & mw;
                lacc0 = h2add(lacc0, p01);
                lacc1 = h2add(lacc1, p23);
                smw[r0 * ATSW + ni * 4 + tig]       = p01;
                smw[(r0 + 8) * ATSW + ni * 4 + tig] = p23;
            }
            __syncwarp();     // P stores visible to own-warp ldmatrix

            // ---- O += P V ----
#pragma unroll
            for (int kg = 0; kg < 4; kg++) {
                uint32_t pa[4];
                ldsm_x4(pa, smb + pofs + (uint32_t)kg * 32);
#pragma unroll
                for (int dp = 0; dp < 4; dp++) {
                    uint32_t vf[4];
                    ldsm_x4_t(vf, Vb + rowoff + (uint32_t)(kg * 16) * ATSB + dp * 32);
                    mma_f16(oacc[2 * dp],     pa, vf);
                    mma_f16(oacc[2 * dp + 1], pa, vf + 2);
                }
            }
            __syncwarp();     // P reads done before next half overwrites it
        }

        if (pre) CP_COMMIT();

        // flush half2 l partials to fp32 once per macro-tile
        {
            float2 f0 = __half22float2(*(__half2*)&lacc0);
            float2 f1 = __half22float2(*(__half2*)&lacc1);
            l0 += f0.x + f0.y;
            l1 += f1.x + f1.y;
        }
    }

    // ---- epilogue: reduce l, normalize, store fp16 context ----
    l0 += __shfl_xor_sync(0xFFFFFFFF, l0, 1);
    l0 += __shfl_xor_sync(0xFFFFFFFF, l0, 2);
    l1 += __shfl_xor_sync(0xFFFFFFFF, l1, 1);
    l1 += __shfl_xor_sync(0xFFFFFFFF, l1, 2);
    float inv0 = (l0 > 0.f) ? 1.f / l0 : 0.f;
    float inv1 = (l1 > 0.f) ? 1.f / l1 : 0.f;

    __half* Cg = g_ch + ((size_t)b * SEQ + q0) * D_MODEL + h * HD;
#pragma unroll
    for (int nd = 0; nd < 8; nd++) {
        int c = nd * 8 + 2 * tig;
        *(uint32_t*)&Cg[(size_t)r0 * D_MODEL + c] =
            pack_h2(oacc[nd][0] * inv0, oacc[nd][1] * inv0);
        *(uint32_t*)&Cg[(size_t)(r0 + 8) * D_MODEL + c] =
            pack_h2(oacc[nd][2] * inv1, oacc[nd][3] * inv1);
    }
}

// ---------------------------------------------------------------------------
// kernel_launch
// inputs: 0 query, 1 key, 2 value, 3 mask(int32), 4 Wq, 5 Wk, 6 Wv, 7 Wo, 8 bo
// ---------------------------------------------------------------------------
extern "C" void kernel_launch(void* const* d_in, const int* in_sizes, int n_in,
                              void* d_out, int out_size)
{
    const int* maskp = (const int*)d_in[3];
    const float* bo  = (const float*)d_in[8];
    float* out = (float*)d_out;

    cudaFuncSetAttribute(gemm_h_kernel,
                         cudaFuncAttributeMaxDynamicSharedMemorySize, GSM_TOT);
    cudaFuncSetAttribute(attn_kernel,
                         cudaFuncAttributeMaxDynamicSharedMemorySize, ATT_SM_BYTES);

    cvt_all_kernel<<<N4_TOTAL / 2048, 256>>>(
        (const float4*)d_in[0], (const float4*)d_in[1], (const float4*)d_in[2],
        (const float4*)d_in[4], (const float4*)d_in[5], (const float4*)d_in[6],
        (const float4*)d_in[7]);

    // Q, K, V projections fused into one launch (blockIdx.z = sel)
    gemm_h_kernel<<<dim3(GN / 128, MTOK / 128, 3), 256, GSM_TOT>>>(bo, nullptr, 0);

    attn_kernel<<<dim3(SEQ / 128, BATCH * NHEADS), 256, ATT_SM_BYTES>>>(maskp);

    gemm_h_kernel<<<dim3(GN / 128, MTOK / 128, 1), 256, GSM_TOT>>>(bo, out, 3);
}

// round 16
// speedup vs baseline: 1.0095x; 1.0095x over previous
#include <cuda_runtime.h>
#include <cuda_fp16.h>
#include <cstdint>
#include <math.h>

#define D_MODEL 1024
#define NHEADS  16
#define HD      64
#define BATCH   2
#define SEQ     2048
#define MTOK    (BATCH * SEQ)   // 4096
#define QSCALE  (0.125f * 1.4426950408889634f)   // 1/sqrt(64) * log2(e)

// fp16 intermediates (device globals; no allocation allowed)
__device__ __half h_qin[MTOK * D_MODEL];
__device__ __half h_kin[MTOK * D_MODEL];
__device__ __half h_vin[MTOK * D_MODEL];
__device__ __half h_wq[D_MODEL * D_MODEL];
__device__ __half h_wk[D_MODEL * D_MODEL];
__device__ __half h_wv[D_MODEL * D_MODEL];
__device__ __half h_wo[D_MODEL * D_MODEL];
__device__ __half g_qh[MTOK * D_MODEL];   // Q proj (pre-scaled by QSCALE)
__device__ __half g_kh[MTOK * D_MODEL];
__device__ __half g_vh[MTOK * D_MODEL];
__device__ __half g_ch[MTOK * D_MODEL];   // attention context

__device__ __forceinline__ uint32_t pack_h2(float lo, float hi) {
    __half2 h = __floats2half2_rn(lo, hi);
    return *(uint32_t*)&h;
}

__device__ __forceinline__ uint32_t h2ex2(uint32_t s) {
    uint32_t y;
    asm("ex2.approx.f16x2 %0, %1;" : "=r"(y) : "r"(s));
    return y;
}

__device__ __forceinline__ uint32_t h2add(uint32_t a, uint32_t b) {
    uint32_t y;
    asm("add.f16x2 %0, %1, %2;" : "=r"(y) : "r"(a), "r"(b));
    return y;
}

__device__ __forceinline__ void mma_f16(float* d, const uint32_t* a, const uint32_t* b) {
    asm volatile(
        "mma.sync.aligned.m16n8k16.row.col.f32.f16.f16.f32 "
        "{%0,%1,%2,%3}, {%4,%5,%6,%7}, {%8,%9}, {%0,%1,%2,%3};"
        : "+f"(d[0]), "+f"(d[1]), "+f"(d[2]), "+f"(d[3])
        : "r"(a[0]), "r"(a[1]), "r"(a[2]), "r"(a[3]), "r"(b[0]), "r"(b[1]));
}

__device__ __forceinline__ void ldsm_x4(uint32_t* r, uint32_t saddr) {
    asm volatile(
        "ldmatrix.sync.aligned.m8n8.x4.shared.b16 {%0,%1,%2,%3}, [%4];"
        : "=r"(r[0]), "=r"(r[1]), "=r"(r[2]), "=r"(r[3]) : "r"(saddr));
}

__device__ __forceinline__ void ldsm_x4_t(uint32_t* r, uint32_t saddr) {
    asm volatile(
        "ldmatrix.sync.aligned.m8n8.x4.trans.shared.b16 {%0,%1,%2,%3}, [%4];"
        : "=r"(r[0]), "=r"(r[1]), "=r"(r[2]), "=r"(r[3]) : "r"(saddr));
}

__device__ __forceinline__ uint32_t smem_u32(const void* p) {
    uint32_t a;
    asm("{ .reg .u64 t; cvta.to.shared.u64 t, %1; cvt.u32.u64 %0, t; }"
        : "=r"(a) : "l"(p));
    return a;
}

// PDL: wait for the producer grid's memory to be visible
__device__ __forceinline__ void pdl_wait() {
    asm volatile("griddepcontrol.wait;" ::: "memory");
}
// PDL: allow dependent grid to begin launching
__device__ __forceinline__ void pdl_launch_dependents() {
    asm volatile("griddepcontrol.launch_dependents;");
}

#define CP16(dst, src) \
    asm volatile("cp.async.cg.shared.global [%0], [%1], 16;" :: "r"(dst), "l"(src))
#define CP_COMMIT() asm volatile("cp.async.commit_group;" ::: "memory")
#define CP_WAIT(n)  asm volatile("cp.async.wait_group %0;" :: "n"(n) : "memory")

// ===========================================================================
// Fused fp32 -> fp16 convert for all 7 tensors in ONE launch (R14 version).
// ===========================================================================
#define N4_IN 1048576
#define N4_W  262144
#define N4_TOTAL (3 * N4_IN + 4 * N4_W)   // 4194304

__global__ void __launch_bounds__(256) cvt_all_kernel(
    const float4* __restrict__ q, const float4* __restrict__ k,
    const float4* __restrict__ v, const float4* __restrict__ wq,
    const float4* __restrict__ wk, const float4* __restrict__ wv,
    const float4* __restrict__ wo)
{
    int i = blockIdx.x * 256 + threadIdx.x;
    const float4* src;
    uint2* dst;
    int j;
    if (i < 3 * N4_IN) {
        int t = i / N4_IN;
        j = i - t * N4_IN;
        src = (t == 0) ? q : (t == 1) ? k : v;
        dst = (uint2*)((t == 0) ? h_qin : (t == 1) ? h_kin : h_vin);
    } else {
        int r = i - 3 * N4_IN;
        int t = r / N4_W;
        j = r - t * N4_W;
        src = (t == 0) ? wq : (t == 1) ? wk : (t == 2) ? wv : wo;
        dst = (uint2*)((t == 0) ? h_wq : (t == 1) ? h_wk : (t == 2) ? h_wv : h_wo);
    }
    float4 val = src[j];
    dst[j] = make_uint2(pack_h2(val.x, val.y), pack_h2(val.z, val.w));
}

// ===========================================================================
// fp16 GEMM (R13 winner + PDL): C[M][N] = A[M][K] * W[N][K]^T
// CTA 128x128, 3-stage cp.async pipeline, interleaved prefetch.
// ===========================================================================
#define GK 1024
#define GN 1024
#define GST 144               // smem row stride bytes (64 halves + 8 pad)
#define GSTW 36
#define GABUF (128 * GSTW)    // words per A (or B) stage
#define GW_B  (3 * GABUF)     // B region word offset
#define GSM_TOT (6 * GABUF * 4)   // 110592 bytes
#define NKIT (GK / 64)        // 16

__global__ void __launch_bounds__(256, 2) gemm_h_kernel(
    const float* __restrict__ bias, float* __restrict__ Cf, int baseSel)
{
    extern __shared__ uint32_t gsm[];
    const uint32_t smb = smem_u32(gsm);
    const int sel = baseSel + blockIdx.z;

    const __half* A;
    const __half* W;
    __half* Ch = nullptr;
    if (sel == 0)      { A = h_qin; W = h_wq; Ch = g_qh; }
    else if (sel == 1) { A = h_kin; W = h_wk; Ch = g_kh; }
    else if (sel == 2) { A = h_vin; W = h_wv; Ch = g_vh; }
    else               { A = g_ch;  W = h_wo; }

    const int tid = threadIdx.x;
    const int wid = tid >> 5;
    const int lane = tid & 31;
    const int g   = lane >> 2;
    const int tig = lane & 3;
    const int wm = wid >> 2;
    const int wn = wid & 3;
    const int bm = blockIdx.y * 128;
    const int bn = blockIdx.x * 128;

    const uint32_t aofs = (uint32_t)(wm * 64 + (lane & 15)) * GST + ((lane >> 4) & 1) * 16;
    const uint32_t bofs = (uint32_t)(wn * 32 + (lane & 7) + ((lane >> 4) & 1) * 8) * GST +
                          ((lane >> 3) & 1) * 16;

    auto issue_stage = [&](int k0, int st) {
        const uint32_t ab = smb + (uint32_t)(st * GABUF) * 4;
        const uint32_t bb = smb + (uint32_t)(GW_B + st * GABUF) * 4;
#pragma unroll
        for (int i = 0; i < 4; i++) {
            int f = tid + i * 256;
            int r = f >> 3;
            int c = f & 7;
            CP16(ab + (uint32_t)r * GST + c * 16, A + (size_t)(bm + r) * GK + k0 + c * 8);
            CP16(bb + (uint32_t)r * GST + c * 16, W + (size_t)(bn + r) * GK + k0 + c * 8);
        }
    };

    float acc[4][4][4];
#pragma unroll
    for (int i = 0; i < 4; i++)
#pragma unroll
        for (int j = 0; j < 4; j++)
#pragma unroll
            for (int r = 0; r < 4; r++) acc[i][j][r] = 0.f;

    // PDL: wait until producer grid's writes (cvt outputs / attn context)
    // are visible before the first cp.async consumes them.
    pdl_wait();

    issue_stage(0, 0);
    CP_COMMIT();
    issue_stage(64, 1);
    CP_COMMIT();

    for (int k = 0; k < NKIT; k++) {
        if (k + 1 < NKIT) CP_WAIT(1); else CP_WAIT(0);
        __syncthreads();

        const int cur = k % 3;
        const uint32_t Ab = smb + (uint32_t)(cur * GABUF) * 4 + aofs;
        const uint32_t Bb = smb + (uint32_t)(GW_B + cur * GABUF) * 4 + bofs;

        const bool pre = (k + 2 < NKIT);
        const int nst = (k + 2) % 3;
        const uint32_t abp = smb + (uint32_t)(nst * GABUF) * 4;
        const uint32_t bbp = smb + (uint32_t)(GW_B + nst * GABUF) * 4;
        const __half* An = A + (size_t)bm * GK + (k + 2) * 64;
        const __half* Wn = W + (size_t)bn * GK + (k + 2) * 64;

#pragma unroll
        for (int kg = 0; kg < 4; kg++) {
            uint32_t afr[4][4];
#pragma unroll
            for (int mi = 0; mi < 4; mi++)
                ldsm_x4(afr[mi], Ab + (uint32_t)(mi * 16) * GST + kg * 32);
            uint32_t bq[2][4];
#pragma unroll
            for (int nb = 0; nb < 2; nb++)
                ldsm_x4(bq[nb], Bb + (uint32_t)(nb * 16) * GST + kg * 32);
#pragma unroll
            for (int mi = 0; mi < 4; mi++) {
                mma_f16(acc[mi][0], afr[mi], bq[0]);
                mma_f16(acc[mi][1], afr[mi], bq[0] + 2);
                mma_f16(acc[mi][2], afr[mi], bq[1]);
                mma_f16(acc[mi][3], afr[mi], bq[1] + 2);
            }
            if (pre) {
                int f = tid + kg * 256;
                int r = f >> 3;
                int c = f & 7;
                CP16(abp + (uint32_t)r * GST + c * 16, An + (size_t)r * GK + c * 8);
                CP16(bbp + (uint32_t)r * GST + c * 16, Wn + (size_t)r * GK + c * 8);
            }
        }
        if (pre) CP_COMMIT();
    }

    // PDL: mainloop done; let the dependent grid start launching while we
    // run the epilogue (its pdl_wait still orders against our final stores).
    pdl_launch_dependents();

    if (sel < 3) {
        const float sc = (sel == 0) ? QSCALE : 1.f;
#pragma unroll
        for (int mi = 0; mi < 4; mi++)
#pragma unroll
            for (int ni = 0; ni < 4; ni++) {
                int row = bm + wm * 64 + mi * 16 + g;
                int col = bn + wn * 32 + ni * 8 + 2 * tig;
                *(uint32_t*)&Ch[(size_t)row * GN + col] =
                    pack_h2(acc[mi][ni][0] * sc, acc[mi][ni][1] * sc);
                *(uint32_t*)&Ch[(size_t)(row + 8) * GN + col] =
                    pack_h2(acc[mi][ni][2] * sc, acc[mi][ni][3] * sc);
            }
    } else {
#pragma unroll
        for (int mi = 0; mi < 4; mi++)
#pragma unroll
            for (int ni = 0; ni < 4; ni++) {
                int row = bm + wm * 64 + mi * 16 + g;
                int col = bn + wn * 32 + ni * 8 + 2 * tig;
                float2 bb = *(const float2*)&bias[col];
                *(float2*)&Cf[(size_t)row * GN + col] =
                    make_float2(acc[mi][ni][0] + bb.x, acc[mi][ni][1] + bb.y);
                *(float2*)&Cf[(size_t)(row + 8) * GN + col] =
                    make_float2(acc[mi][ni][2] + bb.x, acc[mi][ni][3] + bb.y);
            }
    }
}

// ===========================================================================
// fp16 flash attention (R14 winner + PDL): max-free f16x2-exp softmax,
// 128-key macro-tiles, 2-stage cp.async KV double buffer, interleaved
// KV prefetch. Mask ballots run pre-sync (external input).
// ===========================================================================
#define NT2 (SEQ / 128)            // 16 macro-tiles
#define ATSB 144
#define ATSW 36
#define W_K   (128 * ATSW)         // K region word offset (after Q/P)
#define KBUF2 (128 * ATSW)         // words per 128-row K (or V) stage
#define W_V   (W_K + 2 * KBUF2)
#define W_MB  (W_V + 2 * KBUF2)    // 64 mask bitmask words
#define ATT_SM_BYTES ((W_MB + 64) * 4)   // 92416

__global__ void __launch_bounds__(256, 2) attn_kernel(const int* __restrict__ mask)
{
    extern __shared__ uint32_t smw[];
    const uint32_t smb = smem_u32(smw);

    const int tid = threadIdx.x;
    const int wid = tid >> 5;
    const int lane = tid & 31;
    const int g   = lane >> 2;
    const int tig = lane & 3;
    const int bh = blockIdx.y;
    const int b = bh >> 4;
    const int h = bh & 15;
    const int q0 = blockIdx.x * 128;
    const int r0 = wid * 16 + g;

    const __half* Qg = g_qh + ((size_t)b * SEQ + q0) * D_MODEL + h * HD;
    const __half* Kg = g_kh + (size_t)b * SEQ * D_MODEL + h * HD;
    const __half* Vg = g_vh + (size_t)b * SEQ * D_MODEL + h * HD;
    const int* mrow = mask + b * SEQ;

    const uint32_t kofs = (uint32_t)((lane & 7) + ((lane >> 4) & 1) * 8) * ATSB +
                          ((lane >> 3) & 1) * 16;
    const uint32_t pofs = (uint32_t)(wid * 16 + (lane & 15)) * ATSB +
                          ((lane >> 4) & 1) * 16;
    const uint32_t vofs = (uint32_t)((lane & 7) + ((lane >> 3) & 1) * 8) * ATSB +
                          ((lane >> 4) & 1) * 16;

    auto issue_kv = [&](int t, int st) {
        const __half* Kt = Kg + (size_t)t * 128 * D_MODEL;
        const __half* Vt = Vg + (size_t)t * 128 * D_MODEL;
        const uint32_t kb = smb + (uint32_t)(W_K + st * KBUF2) * 4;
        const uint32_t vb = smb + (uint32_t)(W_V + st * KBUF2) * 4;
#pragma unroll
        for (int i = 0; i < 4; i++) {
            int f = tid + i * 256;
            int r = f >> 3;
            int c = f & 7;
            CP16(kb + (uint32_t)r * ATSB + c * 16, Kt + (size_t)r * D_MODEL + c * 8);
            CP16(vb + (uint32_t)r * ATSB + c * 16, Vt + (size_t)r * D_MODEL + c * 8);
        }
    };

    // ---- independent prologue (pre-sync): mask ballots from external input ----
#pragma unroll
    for (int i = 0; i < 8; i++) {
        int w = wid * 8 + i;
        uint32_t bal = __ballot_sync(0xFFFFFFFF, mrow[w * 32 + lane] != 0);
        if (lane == 0) smw[W_MB + w] = bal;
    }

    // PDL: wait for QKV projection outputs before consuming them.
    pdl_wait();

    // ---- stage Q (group 0), macro-tile 0 (group 1) ----
#pragma unroll
    for (int i = 0; i < 4; i++) {
        int f = tid + i * 256;
        int r = f >> 3;
        int c = f & 7;
        CP16(smb + (uint32_t)r * ATSB + c * 16, Qg + (size_t)r * D_MODEL + c * 8);
    }
    CP_COMMIT();
    issue_kv(0, 0);
    CP_COMMIT();

    CP_WAIT(1);               // Q staged (tile 0 may still be in flight)
    __syncthreads();

    uint32_t qf[4][4];
#pragma unroll
    for (int kg = 0; kg < 4; kg++) {
        qf[kg][0] = smw[r0 * ATSW + kg * 8 + tig];
        qf[kg][1] = smw[(r0 + 8) * ATSW + kg * 8 + tig];
        qf[kg][2] = smw[r0 * ATSW + kg * 8 + tig + 4];
        qf[kg][3] = smw[(r0 + 8) * ATSW + kg * 8 + tig + 4];
    }

    float oacc[8][4];
#pragma unroll
    for (int i = 0; i < 8; i++)
#pragma unroll
        for (int j = 0; j < 4; j++) oacc[i][j] = 0.f;
    float l0 = 0.f, l1 = 0.f;

    for (int t = 0; t < NT2; t++) {
        CP_WAIT(0);
        __syncthreads();

        const int cur = t & 1;
        const uint32_t Kb = smb + (uint32_t)(W_K + cur * KBUF2) * 4 + kofs;
        const uint32_t Vb = smb + (uint32_t)(W_V + cur * KBUF2) * 4 + vofs;

        const bool pre = (t + 1 < NT2);
        const int nst = (t + 1) & 1;
        const __half* Kn = Kg + (size_t)(t + 1) * 128 * D_MODEL;
        const __half* Vn = Vg + (size_t)(t + 1) * 128 * D_MODEL;
        const uint32_t kbp = smb + (uint32_t)(W_K + nst * KBUF2) * 4;
        const uint32_t vbp = smb + (uint32_t)(W_V + nst * KBUF2) * 4;

        uint32_t lacc0 = 0u, lacc1 = 0u;   // half2 partial l accumulators

#pragma unroll
        for (int hf = 0; hf < 2; hf++) {
            const uint32_t mb0 = smw[W_MB + 4 * t + 2 * hf];
            const uint32_t mb1 = smw[W_MB + 4 * t + 2 * hf + 1];
            const uint32_t rowoff = (uint32_t)(hf * 64) * ATSB;

            // ---- S = Q K^T (log2 domain) ----
            float sacc[8][4];
#pragma unroll
            for (int i = 0; i < 8; i++)
#pragma unroll
                for (int j = 0; j < 4; j++) sacc[i][j] = 0.f;
#pragma unroll
            for (int kg = 0; kg < 4; kg++) {
#pragma unroll
                for (int nib = 0; nib < 8; nib += 2) {
                    uint32_t kf[4];
                    ldsm_x4(kf, Kb + rowoff + (uint32_t)(nib * 8) * ATSB + kg * 32);
                    mma_f16(sacc[nib],     qf[kg], kf);
                    mma_f16(sacc[nib + 1], qf[kg], kf + 2);
                }
                if (pre) {
                    int s = hf * 4 + kg;
                    int ch = (s < 4) ? s : (s - 4);
                    int f = tid + ch * 256;
                    int r = f >> 3;
                    int c = f & 7;
                    if (s < 4) {
                        CP16(kbp + (uint32_t)r * ATSB + c * 16,
                             Kn + (size_t)r * D_MODEL + c * 8);
                    } else {
                        CP16(vbp + (uint32_t)r * ATSB + c * 16,
                             Vn + (size_t)r * D_MODEL + c * 8);
                    }
                }
            }

            // ---- max-free softmax, f16x2 exp: p = (2^s) & maskword ----
#pragma unroll
            for (int ni = 0; ni < 8; ni++) {
                uint32_t mb = (ni < 4) ? mb0 : mb1;
                int c0 = (ni * 8 + 2 * tig) & 31;
                uint32_t mw = (((mb >> c0) & 1) ? 0x0000FFFFu : 0u) |
                              (((mb >> (c0 + 1)) & 1) ? 0xFFFF0000u : 0u);
                uint32_t p01 = h2ex2(pack_h2(sacc[ni][0], sacc[ni][1])) & mw;
                uint32_t p23 = h2ex2(pack_h2(sacc[ni][2], sacc[ni][3])) & mw;
                lacc0 = h2add(lacc0, p01);
                lacc1 = h2add(lacc1, p23);
                smw[r0 * ATSW + ni * 4 + tig]       = p01;
                smw[(r0 + 8) * ATSW + ni * 4 + tig] = p23;
            }
            __syncwarp();     // P stores visible to own-warp ldmatrix

            // ---- O += P V ----
#pragma unroll
            for (int kg = 0; kg < 4; kg++) {
                uint32_t pa[4];
                ldsm_x4(pa, smb + pofs + (uint32_t)kg * 32);
#pragma unroll
                for (int dp = 0; dp < 4; dp++) {
                    uint32_t vf[4];
                    ldsm_x4_t(vf, Vb + rowoff + (uint32_t)(kg * 16) * ATSB + dp * 32);
                    mma_f16(oacc[2 * dp],     pa, vf);
                    mma_f16(oacc[2 * dp + 1], pa, vf + 2);
                }
            }
            __syncwarp();     // P reads done before next half overwrites it
        }

        if (pre) CP_COMMIT();

        // flush half2 l partials to fp32 once per macro-tile
        {
            float2 f0 = __half22float2(*(__half2*)&lacc0);
            float2 f1 = __half22float2(*(__half2*)&lacc1);
            l0 += f0.x + f0.y;
            l1 += f1.x + f1.y;
        }
    }

    // PDL: mainloop done; let the out-proj GEMM start launching.
    pdl_launch_dependents();

    // ---- epilogue: reduce l, normalize, store fp16 context ----
    l0 += __shfl_xor_sync(0xFFFFFFFF, l0, 1);
    l0 += __shfl_xor_sync(0xFFFFFFFF, l0, 2);
    l1 += __shfl_xor_sync(0xFFFFFFFF, l1, 1);
    l1 += __shfl_xor_sync(0xFFFFFFFF, l1, 2);
    float inv0 = (l0 > 0.f) ? 1.f / l0 : 0.f;
    float inv1 = (l1 > 0.f) ? 1.f / l1 : 0.f;

    __half* Cg = g_ch + ((size_t)b * SEQ + q0) * D_MODEL + h * HD;
#pragma unroll
    for (int nd = 0; nd < 8; nd++) {
        int c = nd * 8 + 2 * tig;
        *(uint32_t*)&Cg[(size_t)r0 * D_MODEL + c] =
            pack_h2(oacc[nd][0] * inv0, oacc[nd][1] * inv0);
        *(uint32_t*)&Cg[(size_t)(r0 + 8) * D_MODEL + c] =
            pack_h2(oacc[nd][2] * inv1, oacc[nd][3] * inv1);
    }
}

// ---------------------------------------------------------------------------
// kernel_launch
// inputs: 0 query, 1 key, 2 value, 3 mask(int32), 4 Wq, 5 Wk, 6 Wv, 7 Wo, 8 bo
// ---------------------------------------------------------------------------
extern "C" void kernel_launch(void* const* d_in, const int* in_sizes, int n_in,
                              void* d_out, int out_size)
{
    const int* maskp = (const int*)d_in[3];
    const float* bo  = (const float*)d_in[8];
    float* out = (float*)d_out;

    cudaFuncSetAttribute(gemm_h_kernel,
                         cudaFuncAttributeMaxDynamicSharedMemorySize, GSM_TOT);
    cudaFuncSetAttribute(attn_kernel,
                         cudaFuncAttributeMaxDynamicSharedMemorySize, ATT_SM_BYTES);

    cvt_all_kernel<<<N4_TOTAL / 256, 256>>>(
        (const float4*)d_in[0], (const float4*)d_in[1], (const float4*)d_in[2],
        (const float4*)d_in[4], (const float4*)d_in[5], (const float4*)d_in[6],
        (const float4*)d_in[7]);

    // PDL launch attribute: allow this grid to launch while its predecessor
    // is still completing; device-side griddepcontrol.wait enforces ordering.
    cudaLaunchAttribute pdlAttr;
    pdlAttr.id = cudaLaunchAttributeProgrammaticStreamSerialization;
    pdlAttr.val.programmaticStreamSerializationAllowed = 1;

    // Q, K, V projections fused into one launch (blockIdx.z = sel)
    {
        cudaLaunchConfig_t cfg = {};
        cfg.gridDim = dim3(GN / 128, MTOK / 128, 3);
        cfg.blockDim = dim3(256, 1, 1);
        cfg.dynamicSmemBytes = GSM_TOT;
        cfg.attrs = &pdlAttr;
        cfg.numAttrs = 1;
        cudaLaunchKernelEx(&cfg, gemm_h_kernel, bo, (float*)nullptr, 0);
    }

    {
        cudaLaunchConfig_t cfg = {};
        cfg.gridDim = dim3(SEQ / 128, BATCH * NHEADS, 1);
        cfg.blockDim = dim3(256, 1, 1);
        cfg.dynamicSmemBytes = ATT_SM_BYTES;
        cfg.attrs = &pdlAttr;
        cfg.numAttrs = 1;
        cudaLaunchKernelEx(&cfg, attn_kernel, maskp);
    }

    {
        cudaLaunchConfig_t cfg = {};
        cfg.gridDim = dim3(GN / 128, MTOK / 128, 1);
        cfg.blockDim = dim3(256, 1, 1);
        cfg.dynamicSmemBytes = GSM_TOT;
        cfg.attrs = &pdlAttr;
        cfg.numAttrs = 1;
        cudaLaunchKernelEx(&cfg, gemm_h_kernel, bo, out, 3);
    }
}